// round 1
// baseline (speedup 1.0000x reference)
#include <cuda_runtime.h>

// ============================================================================
// LocalBranch fused kernel, round 1 (fp32 SIMT, fully fused per-graph CTA).
//
// Pipeline per graph (128 nodes), all inside one CTA:
//   x = relu(LN(H @ W_in + b_in))                       [128, 256]
//   x = x + relu(LN(x @ Wb[k] + bb[k]))   k = 0..2
//   z = LN(x @ W_out + b_out)                           [128, 128]
//   d_ij = sqrt(max(|z_i|^2 + |z_j|^2 - 2 z_i.z_j, 0) + 1e-12)
//   s_i = mean_j d_ij ; w = softmax(s / 0.25) ; v = sum_i w_i z_i
// Output: v_loc [1024,128] followed by w [1024,128]  (float32)
// ============================================================================

namespace lb {

constexpr int TPB   = 512;
constexpr int NODES = 128;
constexpr int IND   = 64;
constexpr int HID   = 256;
constexpr int OUTD  = 128;
constexpr int NBLK  = 3;
constexpr int NG    = 1024;
constexpr int KC    = 16;     // k-chunk for weight staging
constexpr int ZSTR  = 132;    // zT row stride (bank-conflict padding)

constexpr int SX_FLOATS   = NODES * HID;    // 32768  (x buffer)
constexpr int SAUX_FLOATS = NODES * ZSTR;   // 16896  (H tile, then zT)
constexpr int SW_FLOATS   = KC * HID;       // 4096   (weight stage / scratch)
constexpr int SMEM_FLOATS = SX_FLOATS + SAUX_FLOATS + SW_FLOATS;
constexpr int SMEM_BYTES  = SMEM_FLOATS * 4;  // 215040 B

__device__ __forceinline__ float warpsum(float v) {
#pragma unroll
    for (int o = 16; o; o >>= 1) v += __shfl_xor_sync(0xffffffffu, v, o);
    return v;
}

// Register-blocked GEMM: C[128, NCOLS] = X[128, KDIM] @ W[KDIM, NCOLS].
// Thread (wid, lane): rows r0..r0+7 (r0 = wid*8),
// cols c0..c0+3 and (NCOLS==256) c0+128..c0+131 (c0 = lane*4).
// X in SMEM (broadcast loads), W staged chunk-wise global->SMEM with
// register prefetch of the next chunk during compute.
template<int KDIM, int NCOLS>
__device__ __forceinline__ void gemm_tile(
    const float* __restrict__ xin, int xstride,
    const float* __restrict__ Wg,
    float* __restrict__ sw,
    float (&acc)[8][8],
    int r0, int c0, int tid)
{
    constexpr int NCH = KDIM / KC;
    constexpr int V4  = (KC * NCOLS) / (TPB * 4);   // float4s per thread (1 or 2)

    float4 pre[V4];
    {
        const float4* src = reinterpret_cast<const float4*>(Wg);
#pragma unroll
        for (int q = 0; q < V4; ++q) pre[q] = src[tid * V4 + q];
    }
#pragma unroll
    for (int m = 0; m < 8; ++m)
#pragma unroll
        for (int n = 0; n < 8; ++n) acc[m][n] = 0.f;

#pragma unroll 1
    for (int ch = 0; ch < NCH; ++ch) {
        __syncthreads();   // previous consumers of sw (and sx writers) done
        float4* dst = reinterpret_cast<float4*>(sw);
#pragma unroll
        for (int q = 0; q < V4; ++q) dst[tid * V4 + q] = pre[q];
        __syncthreads();
        if (ch + 1 < NCH) {
            const float4* src =
                reinterpret_cast<const float4*>(Wg + (size_t)(ch + 1) * KC * NCOLS);
#pragma unroll
            for (int q = 0; q < V4; ++q) pre[q] = src[tid * V4 + q];
        }
        const float* xrow = xin + ch * KC;
#pragma unroll 2
        for (int kk = 0; kk < KC; kk += 2) {
            float2 xv[8];
#pragma unroll
            for (int m = 0; m < 8; ++m)
                xv[m] = *reinterpret_cast<const float2*>(
                    &xrow[(r0 + m) * xstride + kk]);
#pragma unroll
            for (int t = 0; t < 2; ++t) {
                float4 wA = *reinterpret_cast<const float4*>(
                    &sw[(kk + t) * NCOLS + c0]);
                float4 wB;
                if constexpr (NCOLS == 256)
                    wB = *reinterpret_cast<const float4*>(
                        &sw[(kk + t) * NCOLS + c0 + 128]);
#pragma unroll
                for (int m = 0; m < 8; ++m) {
                    float xs = t ? xv[m].y : xv[m].x;
                    acc[m][0] = fmaf(xs, wA.x, acc[m][0]);
                    acc[m][1] = fmaf(xs, wA.y, acc[m][1]);
                    acc[m][2] = fmaf(xs, wA.z, acc[m][2]);
                    acc[m][3] = fmaf(xs, wA.w, acc[m][3]);
                    if constexpr (NCOLS == 256) {
                        acc[m][4] = fmaf(xs, wB.x, acc[m][4]);
                        acc[m][5] = fmaf(xs, wB.y, acc[m][5]);
                        acc[m][6] = fmaf(xs, wB.z, acc[m][6]);
                        acc[m][7] = fmaf(xs, wB.w, acc[m][7]);
                    }
                }
            }
        }
    }
}

// LN(+bias) -> relu -> (optional residual) -> write back into sx.
template<bool RES>
__device__ __forceinline__ void epi256(
    float (&acc)[8][8], float* __restrict__ sx,
    const float* __restrict__ bias, const float* __restrict__ gamma,
    const float* __restrict__ beta, int r0, int c0)
{
    float4 bA = *reinterpret_cast<const float4*>(&bias[c0]);
    float4 bB = *reinterpret_cast<const float4*>(&bias[c0 + 128]);
    float4 gA = *reinterpret_cast<const float4*>(&gamma[c0]);
    float4 gB = *reinterpret_cast<const float4*>(&gamma[c0 + 128]);
    float4 eA = *reinterpret_cast<const float4*>(&beta[c0]);
    float4 eB = *reinterpret_cast<const float4*>(&beta[c0 + 128]);
    float bv[8] = {bA.x, bA.y, bA.z, bA.w, bB.x, bB.y, bB.z, bB.w};
    float gv[8] = {gA.x, gA.y, gA.z, gA.w, gB.x, gB.y, gB.z, gB.w};
    float ev[8] = {eA.x, eA.y, eA.z, eA.w, eB.x, eB.y, eB.z, eB.w};
    float mu[8], rs[8];
#pragma unroll
    for (int m = 0; m < 8; ++m) {
        float s1 = 0.f, s2 = 0.f;
#pragma unroll
        for (int n = 0; n < 8; ++n) {
            float v = acc[m][n] + bv[n];
            acc[m][n] = v;
            s1 += v;
            s2 = fmaf(v, v, s2);
        }
        s1 = warpsum(s1);
        s2 = warpsum(s2);
        float m_ = s1 * (1.f / 256.f);
        mu[m] = m_;
        rs[m] = rsqrtf(fmaf(-m_, m_, s2 * (1.f / 256.f)) + 1e-5f);
    }
    __syncthreads();   // all GEMM reads of sx complete before we overwrite
#pragma unroll
    for (int m = 0; m < 8; ++m) {
        float o[8];
#pragma unroll
        for (int n = 0; n < 8; ++n) {
            float v = (acc[m][n] - mu[m]) * rs[m];
            v = fmaf(v, gv[n], ev[n]);
            o[n] = fmaxf(v, 0.f);
        }
        float* row = &sx[(r0 + m) * HID];
        if (RES) {
            float4 oA = *reinterpret_cast<const float4*>(&row[c0]);
            float4 oB = *reinterpret_cast<const float4*>(&row[c0 + 128]);
            o[0] += oA.x; o[1] += oA.y; o[2] += oA.z; o[3] += oA.w;
            o[4] += oB.x; o[5] += oB.y; o[6] += oB.z; o[7] += oB.w;
        }
        *reinterpret_cast<float4*>(&row[c0]) = make_float4(o[0], o[1], o[2], o[3]);
        *reinterpret_cast<float4*>(&row[c0 + 128]) =
            make_float4(o[4], o[5], o[6], o[7]);
    }
}

__global__ void __launch_bounds__(TPB, 1)
fused_local_branch(const float* __restrict__ H,
                   const float* __restrict__ W_in, const float* __restrict__ b_in,
                   const float* __restrict__ g_in, const float* __restrict__ be_in,
                   const float* __restrict__ Wb, const float* __restrict__ bbias,
                   const float* __restrict__ gb, const float* __restrict__ betab,
                   const float* __restrict__ W_out, const float* __restrict__ b_out,
                   const float* __restrict__ g_out, const float* __restrict__ be_out,
                   float* __restrict__ out)
{
    extern __shared__ float sm[];
    float* sx   = sm;                          // [128][256]
    float* saux = sm + SX_FLOATS;              // H tile, then zT [128][132]
    float* sw   = sm + SX_FLOATS + SAUX_FLOATS;// weight stage / scratch

    const int tid  = threadIdx.x;
    const int lane = tid & 31;
    const int wid  = tid >> 5;
    const int r0   = wid * 8;
    const int c0   = lane * 4;
    const int g    = blockIdx.x;

    // --- load H tile [128,64] into saux ---
    {
        const float4* src =
            reinterpret_cast<const float4*>(H + (size_t)g * NODES * IND);
        float4* dst = reinterpret_cast<float4*>(saux);
#pragma unroll
        for (int q = 0; q < (NODES * IND / 4) / TPB; ++q)   // 4 iters
            dst[tid + q * TPB] = src[tid + q * TPB];
    }
    // (gemm_tile's internal double __syncthreads orders these STS before use)

    float acc[8][8];

    // --- stem: x = relu(LN(H @ W_in + b_in)) ---
    gemm_tile<IND, HID>(saux, IND, W_in, sw, acc, r0, c0, tid);
    epi256<false>(acc, sx, b_in, g_in, be_in, r0, c0);

    // --- residual blocks ---
    for (int blk = 0; blk < NBLK; ++blk) {
        gemm_tile<HID, HID>(sx, HID, Wb + (size_t)blk * HID * HID, sw, acc,
                            r0, c0, tid);
        epi256<true>(acc, sx, bbias + blk * HID, gb + blk * HID,
                     betab + blk * HID, r0, c0);
    }

    // --- head: z = LN(x @ W_out + b_out), stored transposed zT[dim][node] ---
    gemm_tile<HID, OUTD>(sx, HID, W_out, sw, acc, r0, c0, tid);
    {
        float4 b4 = *reinterpret_cast<const float4*>(&b_out[c0]);
        float4 g4 = *reinterpret_cast<const float4*>(&g_out[c0]);
        float4 e4 = *reinterpret_cast<const float4*>(&be_out[c0]);
        float bv[4] = {b4.x, b4.y, b4.z, b4.w};
        float gv[4] = {g4.x, g4.y, g4.z, g4.w};
        float ev[4] = {e4.x, e4.y, e4.z, e4.w};
#pragma unroll
        for (int m = 0; m < 8; ++m) {
            float s1 = 0.f, s2 = 0.f;
#pragma unroll
            for (int n = 0; n < 4; ++n) {
                float v = acc[m][n] + bv[n];
                acc[m][n] = v;
                s1 += v;
                s2 = fmaf(v, v, s2);
            }
            s1 = warpsum(s1);
            s2 = warpsum(s2);
            float mu = s1 * (1.f / 128.f);
            float rs = rsqrtf(fmaf(-mu, mu, s2 * (1.f / 128.f)) + 1e-5f);
#pragma unroll
            for (int n = 0; n < 4; ++n) {
                float z = fmaf((acc[m][n] - mu) * rs, gv[n], ev[n]);
                saux[(c0 + n) * ZSTR + (r0 + m)] = z;   // zT[dim][node]
            }
        }
    }
    __syncthreads();

    // --- squared norms sq[i], zero s accumulator ---
    if (tid < NODES) {
        float s = 0.f;
#pragma unroll 4
        for (int d = 0; d < OUTD; ++d) {
            float v = saux[d * ZSTR + tid];
            s = fmaf(v, v, s);
        }
        sw[tid] = s;                                    // sq
    } else if (tid >= TPB - NODES) {
        sw[NODES + (tid - (TPB - NODES))] = 0.f;        // s sums
    }
    __syncthreads();

    // --- pairwise: thread covers i = c0..c0+3 (lanes), j = r0..r0+7 (warps) ---
    {
        float dot[8][4];
#pragma unroll
        for (int j = 0; j < 8; ++j)
#pragma unroll
            for (int n = 0; n < 4; ++n) dot[j][n] = 0.f;

#pragma unroll 2
        for (int d = 0; d < OUTD; ++d) {
            float4 zi = *reinterpret_cast<const float4*>(&saux[d * ZSTR + c0]);
#pragma unroll
            for (int j = 0; j < 8; ++j) {
                float zj = saux[d * ZSTR + r0 + j];     // broadcast
                dot[j][0] = fmaf(zj, zi.x, dot[j][0]);
                dot[j][1] = fmaf(zj, zi.y, dot[j][1]);
                dot[j][2] = fmaf(zj, zi.z, dot[j][2]);
                dot[j][3] = fmaf(zj, zi.w, dot[j][3]);
            }
        }
        float sqi[4];
#pragma unroll
        for (int n = 0; n < 4; ++n) sqi[n] = sw[c0 + n];
        float sacc[4] = {0.f, 0.f, 0.f, 0.f};
#pragma unroll
        for (int j = 0; j < 8; ++j) {
            float sqj = sw[r0 + j];
#pragma unroll
            for (int n = 0; n < 4; ++n) {
                float d2 = sqi[n] + sqj - 2.f * dot[j][n];
                sacc[n] += sqrtf(fmaxf(d2, 0.f) + 1e-12f);
            }
        }
#pragma unroll
        for (int n = 0; n < 4; ++n)
            atomicAdd(&sw[NODES + c0 + n], sacc[n]);
    }
    __syncthreads();

    // --- softmax over 128 logits (warp 0): logits = (ssum/128)/TAU ---
    if (wid == 0) {
        const float scale = 1.f / (128.f * 0.25f);
        float sv[4], mx = -1e30f;
#pragma unroll
        for (int q = 0; q < 4; ++q) {
            sv[q] = sw[NODES + lane + 32 * q] * scale;
            mx = fmaxf(mx, sv[q]);
        }
#pragma unroll
        for (int o = 16; o; o >>= 1)
            mx = fmaxf(mx, __shfl_xor_sync(0xffffffffu, mx, o));
        float e[4], se = 0.f;
#pragma unroll
        for (int q = 0; q < 4; ++q) {
            e[q] = expf(sv[q] - mx);
            se += e[q];
        }
        se = warpsum(se);
        float inv = 1.f / se;
#pragma unroll
        for (int q = 0; q < 4; ++q) {
            float w_ = e[q] * inv;
            int i = lane + 32 * q;
            sw[2 * NODES + i] = w_;
            out[(size_t)NG * OUTD + (size_t)g * NODES + i] = w_;
        }
    }
    __syncthreads();

    // --- v[d] = sum_i w_i * z[i][d] ---
    if (tid < OUTD) {
        float a = 0.f;
#pragma unroll 4
        for (int i = 0; i < NODES; ++i)
            a = fmaf(sw[2 * NODES + i], saux[tid * ZSTR + i], a);
        out[(size_t)g * OUTD + tid] = a;
    }
}

}  // namespace lb

extern "C" void kernel_launch(void* const* d_in, const int* in_sizes, int n_in,
                              void* d_out, int out_size)
{
    (void)in_sizes; (void)n_in; (void)out_size;
    const float* H     = (const float*)d_in[0];
    // d_in[1] = batch_ptr (uniform graphs; unused)
    const float* W_in  = (const float*)d_in[2];
    const float* b_in  = (const float*)d_in[3];
    const float* g_in  = (const float*)d_in[4];
    const float* be_in = (const float*)d_in[5];
    const float* Wb    = (const float*)d_in[6];
    const float* bb    = (const float*)d_in[7];
    const float* gb    = (const float*)d_in[8];
    const float* betab = (const float*)d_in[9];
    const float* W_out = (const float*)d_in[10];
    const float* b_out = (const float*)d_in[11];
    const float* g_out = (const float*)d_in[12];
    const float* be_out= (const float*)d_in[13];
    float* out = (float*)d_out;

    cudaFuncSetAttribute(lb::fused_local_branch,
                         cudaFuncAttributeMaxDynamicSharedMemorySize,
                         lb::SMEM_BYTES);

    lb::fused_local_branch<<<lb::NG, lb::TPB, lb::SMEM_BYTES>>>(
        H, W_in, b_in, g_in, be_in, Wb, bb, gb, betab,
        W_out, b_out, g_out, be_out, out);
}